// round 14
// baseline (speedup 1.0000x reference)
#include <cuda_runtime.h>
#include <cuda_bf16.h>
#include <cstdint>
#include <math.h>

#define B     64
#define T     256
#define U     1024
#define G3    3072
#define NBLK  128
#define NT    256

// h packed in MMA A-fragment order:
// [par][ ((bt*64 + kk)*2 + half)*32 + lane ] -> uint4
__device__ __align__(16) uint4 g_hpk[2][4 * 64 * 2 * 32];
// per k-eighth dependency counters, padded to 128B (one L2 line each)
__device__ __align__(128) unsigned g_flag[8 * 32];
__device__ unsigned g_bar_cnt, g_bar_gen;

// ---- SMEM layout (bytes) ----
#define SM_W     0
#define W_NSTR   2064
#define W_PSTR   49536
#define SM_REC   99072              // float [8 plane][64][26]
#define REC_PL   1664               // floats per plane
#define SMEM_TOTAL (99072 + 8*6656) // 152320

// ---- PTX helpers ----
__device__ __forceinline__ uint32_t smem_u32(const void* p) {
    uint32_t a;
    asm("{ .reg .u64 t; cvta.to.shared.u64 t, %1; cvt.u32.u64 %0, t; }" : "=r"(a) : "l"(p));
    return a;
}
__device__ __forceinline__ void ldsm2(uint32_t* r, uint32_t addr) {
    asm volatile("ldmatrix.sync.aligned.m8n8.x2.shared.b16 {%0,%1}, [%2];"
                 : "=r"(r[0]), "=r"(r[1]) : "r"(addr));
}
__device__ __forceinline__ void ldsm4(uint32_t* r, uint32_t addr) {
    asm volatile("ldmatrix.sync.aligned.m8n8.x4.shared.b16 {%0,%1,%2,%3}, [%4];"
                 : "=r"(r[0]), "=r"(r[1]), "=r"(r[2]), "=r"(r[3]) : "r"(addr));
}
__device__ __forceinline__ void mma4(float* c, const uint4& a, uint32_t b0, uint32_t b1) {
    asm volatile("mma.sync.aligned.m16n8k16.row.col.f32.bf16.bf16.f32 "
                 "{%0,%1,%2,%3}, {%4,%5,%6,%7}, {%8,%9}, {%0,%1,%2,%3};"
                 : "+f"(c[0]), "+f"(c[1]), "+f"(c[2]), "+f"(c[3])
                 : "r"(a.x), "r"(a.y), "r"(a.z), "r"(a.w), "r"(b0), "r"(b1));
}
__device__ __forceinline__ void wait_flag(unsigned* f, unsigned tgt) {
    unsigned g;
    while (1) {
        asm volatile("ld.acquire.gpu.u32 %0, [%1];" : "=r"(g) : "l"(f));
        if ((int)(g - tgt) >= 0) break;
        __nanosleep(32);
    }
}
__device__ __forceinline__ void arrive_flag(unsigned* f) {
    asm volatile("red.release.gpu.global.add.u32 [%0], 1;" :: "l"(f));
}

// startup-only grid barrier
__device__ __forceinline__ void grid_barrier() {
    __syncthreads();
    if (threadIdx.x == 0) {
        unsigned gen0;
        asm volatile("ld.acquire.gpu.u32 %0, [%1];" : "=r"(gen0) : "l"(&g_bar_gen));
        unsigned prev;
        asm volatile("atom.release.gpu.global.add.u32 %0, [%1], 1;" : "=r"(prev) : "l"(&g_bar_cnt));
        if (prev == NBLK - 1) {
            asm volatile("st.relaxed.gpu.global.u32 [%0], 0;" :: "l"(&g_bar_cnt));
            asm volatile("red.release.gpu.global.add.u32 [%0], 1;" :: "l"(&g_bar_gen));
        } else {
            unsigned g;
            do { asm volatile("ld.acquire.gpu.u32 %0, [%1];" : "=r"(g) : "l"(&g_bar_gen)); } while (g == gen0);
        }
    }
    __syncthreads();
}

// pack a thread's 2 units (b, uu0=2*up): hi pair as u32, lo pair at +512B
// (round-7 verified layout)
__device__ __forceinline__ void pack_h(int buf, int b, int up, int u0, float2 hn) {
    __nv_bfloat16 h0 = __float2bfloat16(hn.x);
    __nv_bfloat16 h1 = __float2bfloat16(hn.y);
    __nv_bfloat16 l0 = __float2bfloat16(hn.x - __bfloat162float(h0));
    __nv_bfloat16 l1 = __float2bfloat16(hn.y - __bfloat162float(h1));
    uint32_t hip = (uint32_t)__bfloat16_as_ushort(h0) | ((uint32_t)__bfloat16_as_ushort(h1) << 16);
    uint32_t lop = (uint32_t)__bfloat16_as_ushort(l0) | ((uint32_t)__bfloat16_as_ushort(l1) << 16);
    int bt = b >> 4, kk = u0 >> 4;
    int r  = b & 15;
    int lane = (r & 7) * 4 + up;
    int reg  = ((r >> 3) & 1) + (((u0 >> 3) & 1) << 1);
    uint32_t* dst = (uint32_t*)(g_hpk[buf] + (size_t)((bt * 64 + kk) * 2) * 32 + lane) + reg;
    *dst = hip;
    *(dst + 128) = lop;
}

__global__ void __launch_bounds__(NT, 1)
gru_all(const int* __restrict__ x, const float* __restrict__ hidden,
        const float* __restrict__ Win, const float* __restrict__ Wrec,
        const float* __restrict__ bin, const float* __restrict__ brec,
        float* __restrict__ out) {
    extern __shared__ __align__(1024) char smem[];
    const uint32_t sbase = smem_u32(smem);
    float* rec_s = (float*)(smem + SM_REC);
    const int tid = threadIdx.x;
    const int wid = tid >> 5;
    const int l   = tid & 31;
    const int blk = blockIdx.x;
    const int u0  = blk * 8;

    // ---- one-time: W_rec slice -> bf16 hi/lo in SMEM [pass][n][k] ----
    for (int idx = tid; idx < 24 * U; idx += NT) {
        int k = idx / 24;
        int j = idx - k * 24;
        int gate = j >> 3, uu = j & 7;
        float w = Wrec[(size_t)k * G3 + gate * U + u0 + uu];
        __nv_bfloat16 hi = __float2bfloat16(w);
        __nv_bfloat16 lo = __float2bfloat16(w - __bfloat162float(hi));
        *(__nv_bfloat16*)(smem + SM_W + j * W_NSTR + k * 2) = hi;
        *(__nv_bfloat16*)(smem + SM_W + W_PSTR + j * W_NSTR + k * 2) = lo;
    }

    // ---- gate mapping: 256 threads, 2 units each: (b, uu0=2*up) ----
    const int b   = tid >> 2;
    const int up  = tid & 3;
    const int uu0 = up * 2;

    const float2 bi0 = *(const float2*)&bin[0 * U + u0 + uu0];
    const float2 bi1 = *(const float2*)&bin[1 * U + u0 + uu0];
    const float2 bi2 = *(const float2*)&bin[2 * U + u0 + uu0];
    const float2 br0 = *(const float2*)&brec[0 * U + u0 + uu0];
    const float2 br1 = *(const float2*)&brec[1 * U + u0 + uu0];
    const float2 br2 = *(const float2*)&brec[2 * U + u0 + uu0];
    const float czx = bi0.x + br0.x, czy = bi0.y + br0.y;
    const float crx = bi1.x + br1.x, cry = bi1.y + br1.y;
    float2 hold = *(const float2*)&hidden[(size_t)b * U + u0 + uu0];
    int tok = x[b * T];

    // ---- warp MMA mapping: 8 warps, warp = k-eighth kq; all 4 batch-tiles ----
    const int kq = wid;
    const uint32_t boff4 = (uint32_t)((l >> 4) * 8 + (l & 7)) * W_NSTR + ((l >> 3) & 1) * 16;
    const uint32_t boff2 = (uint32_t)(l & 7) * W_NSTR + (l & 8) * 2;
    const int grp = blk >> 4;

    unsigned fbase = *(volatile unsigned*)&g_flag[kq * 32];
    grid_barrier();

    // ---- preload W_hi fragments into registers (loop-invariant) ----
    uint32_t wh[8][6];
    #pragma unroll
    for (int kt = 0; kt < 8; kt++) {
        uint32_t wb = sbase + SM_W + (uint32_t)(kq * 8 + kt) * 32;
        ldsm4(&wh[kt][0], wb + boff4);
        ldsm2(&wh[kt][4], wb + 16 * W_NSTR + boff2);
    }

    // publish h0 into buffer 0
    pack_h(0, b, up, u0, hold);
    __syncthreads();
    if (tid == 0) arrive_flag(&g_flag[grp * 32]);

    for (int t = 0; t < T; t++) {
        const int par = t & 1;

        // gate-input loads issued before the flag wait
        const float2 xw0 = *(const float2*)&Win[(size_t)tok * G3 + 0 * U + u0 + uu0];
        const float2 xw1 = *(const float2*)&Win[(size_t)tok * G3 + 1 * U + u0 + uu0];
        const float2 xw2 = *(const float2*)&Win[(size_t)tok * G3 + 2 * U + u0 + uu0];
        int tok_n = (t + 1 < T) ? x[b * T + t + 1] : 0;

        // wait for the 16 producer CTAs of this warp's k-eighth
        if (l == 0) wait_flag(&g_flag[kq * 32], fbase + 16u * (t + 1));
        __syncwarp();

        // ---- GEMM: 8 k-tiles, 4 batch-tiles, W_hi from registers ----
        float acc[4][3][4];
        #pragma unroll
        for (int bt = 0; bt < 4; bt++)
            #pragma unroll
            for (int nt = 0; nt < 3; nt++)
                #pragma unroll
                for (int e = 0; e < 4; e++) acc[bt][nt][e] = 0.f;

        const uint4* pA[4];
        #pragma unroll
        for (int bt = 0; bt < 4; bt++)
            pA[bt] = g_hpk[par] + (size_t)((bt * 64 + kq * 8) * 2) * 32 + l;

        uint4 Ah[2][4], Al[2][4];
        #pragma unroll
        for (int s = 0; s < 2; s++)
            #pragma unroll
            for (int bt = 0; bt < 4; bt++) {
                Ah[s][bt] = __ldcg(pA[bt] + s * 64);
                Al[s][bt] = __ldcg(pA[bt] + s * 64 + 32);
            }

        #pragma unroll
        for (int kt = 0; kt < 8; kt++) {
            const int s = kt & 1;
            uint4 ch0 = Ah[s][0], ch1 = Ah[s][1], ch2 = Ah[s][2], ch3 = Ah[s][3];
            uint4 cl0 = Al[s][0], cl1 = Al[s][1], cl2 = Al[s][2], cl3 = Al[s][3];
            if (kt < 6) {
                #pragma unroll
                for (int bt = 0; bt < 4; bt++) {
                    Ah[s][bt] = __ldcg(pA[bt] + (kt + 2) * 64);
                    Al[s][bt] = __ldcg(pA[bt] + (kt + 2) * 64 + 32);
                }
            }
            // W_lo fragments for this kt (only SMEM reads in the loop)
            uint32_t bl01[4], bl2[2];
            uint32_t wbl = sbase + SM_W + W_PSTR + (uint32_t)(kq * 8 + kt) * 32;
            ldsm4(bl01, wbl + boff4);
            ldsm2(bl2,  wbl + 16 * W_NSTR + boff2);

            // term 1: h_hi @ W_hi (12 independent accs)
            mma4(acc[0][0], ch0, wh[kt][0], wh[kt][1]);
            mma4(acc[0][1], ch0, wh[kt][2], wh[kt][3]);
            mma4(acc[0][2], ch0, wh[kt][4], wh[kt][5]);
            mma4(acc[1][0], ch1, wh[kt][0], wh[kt][1]);
            mma4(acc[1][1], ch1, wh[kt][2], wh[kt][3]);
            mma4(acc[1][2], ch1, wh[kt][4], wh[kt][5]);
            mma4(acc[2][0], ch2, wh[kt][0], wh[kt][1]);
            mma4(acc[2][1], ch2, wh[kt][2], wh[kt][3]);
            mma4(acc[2][2], ch2, wh[kt][4], wh[kt][5]);
            mma4(acc[3][0], ch3, wh[kt][0], wh[kt][1]);
            mma4(acc[3][1], ch3, wh[kt][2], wh[kt][3]);
            mma4(acc[3][2], ch3, wh[kt][4], wh[kt][5]);
            // term 2: h_hi @ W_lo
            mma4(acc[0][0], ch0, bl01[0], bl01[1]);
            mma4(acc[0][1], ch0, bl01[2], bl01[3]);
            mma4(acc[0][2], ch0, bl2[0],  bl2[1]);
            mma4(acc[1][0], ch1, bl01[0], bl01[1]);
            mma4(acc[1][1], ch1, bl01[2], bl01[3]);
            mma4(acc[1][2], ch1, bl2[0],  bl2[1]);
            mma4(acc[2][0], ch2, bl01[0], bl01[1]);
            mma4(acc[2][1], ch2, bl01[2], bl01[3]);
            mma4(acc[2][2], ch2, bl2[0],  bl2[1]);
            mma4(acc[3][0], ch3, bl01[0], bl01[1]);
            mma4(acc[3][1], ch3, bl01[2], bl01[3]);
            mma4(acc[3][2], ch3, bl2[0],  bl2[1]);
            // term 3: h_lo @ W_hi
            mma4(acc[0][0], cl0, wh[kt][0], wh[kt][1]);
            mma4(acc[0][1], cl0, wh[kt][2], wh[kt][3]);
            mma4(acc[0][2], cl0, wh[kt][4], wh[kt][5]);
            mma4(acc[1][0], cl1, wh[kt][0], wh[kt][1]);
            mma4(acc[1][1], cl1, wh[kt][2], wh[kt][3]);
            mma4(acc[1][2], cl1, wh[kt][4], wh[kt][5]);
            mma4(acc[2][0], cl2, wh[kt][0], wh[kt][1]);
            mma4(acc[2][1], cl2, wh[kt][2], wh[kt][3]);
            mma4(acc[2][2], cl2, wh[kt][4], wh[kt][5]);
            mma4(acc[3][0], cl3, wh[kt][0], wh[kt][1]);
            mma4(acc[3][1], cl3, wh[kt][2], wh[kt][3]);
            mma4(acc[3][2], cl3, wh[kt][4], wh[kt][5]);
        }

        // ---- epilogue: partials -> plane kq (all 64 batches) ----
        {
            float* pl = rec_s + kq * REC_PL;
            int row = l >> 2, c2 = (l & 3) * 2;
            #pragma unroll
            for (int bt = 0; bt < 4; bt++) {
                int bb0 = bt * 16 + row;
                #pragma unroll
                for (int nt = 0; nt < 3; nt++) {
                    int j0 = nt * 8 + c2;
                    *(float2*)&pl[bb0 * 26 + j0]       = make_float2(acc[bt][nt][0], acc[bt][nt][1]);
                    *(float2*)&pl[(bb0 + 8) * 26 + j0] = make_float2(acc[bt][nt][2], acc[bt][nt][3]);
                }
            }
        }
        __syncthreads();

        // ---- gates: 256 threads, 2 units each ----
        {
            float rzx = czx, rzy = czy, rrx = crx, rry = cry;
            float rhx = br2.x, rhy = br2.y;
            #pragma unroll
            for (int p = 0; p < 8; p++) {
                const float* pl = rec_s + p * REC_PL + b * 26;
                float2 a0 = *(const float2*)&pl[0 + uu0];
                float2 a1 = *(const float2*)&pl[8 + uu0];
                float2 a2 = *(const float2*)&pl[16 + uu0];
                rzx += a0.x; rzy += a0.y;
                rrx += a1.x; rry += a1.y;
                rhx += a2.x; rhy += a2.y;
            }
            float zx = __fdividef(1.f, 1.f + __expf(-(xw0.x + rzx)));
            float zy = __fdividef(1.f, 1.f + __expf(-(xw0.y + rzy)));
            float rx = __fdividef(1.f, 1.f + __expf(-(xw1.x + rrx)));
            float ry = __fdividef(1.f, 1.f + __expf(-(xw1.y + rry)));
            float tax = xw2.x + bi2.x + rx * rhx;
            float tay = xw2.y + bi2.y + ry * rhy;
            float hhx = 1.f - __fdividef(2.f, __expf(2.f * tax) + 1.f);
            float hhy = 1.f - __fdividef(2.f, __expf(2.f * tay) + 1.f);
            float2 hn;
            hn.x = zx * hold.x + (1.f - zx) * hhx;
            hn.y = zy * hold.y + (1.f - zy) * hhy;
            hold = hn;
            pack_h(par ^ 1, b, up, u0, hn);
            __syncthreads();
            if (tid == 0 && t < T - 1) arrive_flag(&g_flag[grp * 32]);
            *(float2*)&out[((size_t)b * T + t) * U + u0 + uu0] = hn;
            if (t == T - 1)
                *(float2*)&out[(size_t)B * T * U + (size_t)b * U + u0 + uu0] = hn;
            tok = tok_n;
        }
    }
}

extern "C" void kernel_launch(void* const* d_in, const int* in_sizes, int n_in,
                              void* d_out, int out_size) {
    const int*   x      = (const int*)d_in[0];
    const float* hidden = (const float*)d_in[1];
    const float* Win    = (const float*)d_in[2];
    const float* Wrec   = (const float*)d_in[3];
    const float* bin    = (const float*)d_in[4];
    const float* brec   = (const float*)d_in[5];
    float* out = (float*)d_out;

    cudaFuncSetAttribute(gru_all, cudaFuncAttributeMaxDynamicSharedMemorySize, SMEM_TOTAL);
    gru_all<<<NBLK, NT, SMEM_TOTAL>>>(x, hidden, Win, Wrec, bin, brec, out);
}